// round 6
// baseline (speedup 1.0000x reference)
#include <cuda_runtime.h>
#include <cstdint>

#define Bn  16
#define Nn  1024

// Scratch (device globals; no allocation allowed)
__device__ __align__(16) float g_T[Bn * Nn * 96];     // x @ W            [row][ec]
__device__ __align__(16) float g_S[Bn * Nn * 96];     // x @ W0 + b0      [row][ec]
__device__ __align__(16) float g_sagg[Bn * Nn * 96];  // dis[m,e] * T     [row][ec]  (= B'[k'][c] flat)
__device__ __align__(16) float g_dis[Bn * Nn * 3];    // deg^-1/2         [row][e]

#define FFMA2(d, a, b) \
    asm volatile("fma.rn.f32x2 %0, %1, %2, %0;" : "+l"(d) : "l"(a), "l"(b))
#define DUP2(d, a) \
    asm volatile("mov.b64 %0, {%1,%1};" : "=l"(d) : "f"(a))
#define UNPACK2(lo, hi, v) \
    asm volatile("mov.b64 {%0,%1}, %2;" : "=f"(lo), "=f"(hi) : "l"(v))
#define GETC(v, j) ((j) == 0 ? (v).x : (j) == 1 ? (v).y : (j) == 2 ? (v).z : (v).w)

// ---------------------------------------------------------------------------
// Kernel 1: T = x@W, S = x@W0 + b0.  Block=384 (12 warps) covers 32 rows.
// Warp g -> output columns g*16..+15 for all 32 rows (lane = row): weight
// reads warp-broadcast, xs pad-33 conflict-free.
// ---------------------------------------------------------------------------
__global__ __launch_bounds__(384) void prep_kernel(
    const float* __restrict__ x,
    const float* __restrict__ W,
    const float* __restrict__ W0,
    const float* __restrict__ b0)
{
    __shared__ __align__(16) float Wc[32 * 192];
    __shared__ float b0s[96];
    __shared__ float xs[32][33];

    int t = threadIdx.x;
    for (int i = t; i < 32 * 192; i += 384) {
        int k = i / 192, j = i % 192;
        Wc[i] = (j < 96) ? W[k * 96 + j] : W0[k * 96 + (j - 96)];
    }
    if (t < 96) b0s[t] = b0[t];

    int row0 = blockIdx.x * 32;
    for (int i = t; i < 32 * 32; i += 384)
        xs[i >> 5][i & 31] = x[(size_t)(row0 + (i >> 5)) * 32 + (i & 31)];
    __syncthreads();

    int g = t >> 5, r = t & 31;
    int row = row0 + r;

    float acc[16];
#pragma unroll
    for (int j = 0; j < 16; j++) acc[j] = 0.f;

#pragma unroll 4
    for (int k = 0; k < 32; k++) {
        float xv = xs[r][k];
        const float4* wp = (const float4*)&Wc[k * 192 + g * 16];   // broadcast
        float4 w0v = wp[0], w1v = wp[1], w2v = wp[2], w3v = wp[3];
        acc[0]  += xv * w0v.x; acc[1]  += xv * w0v.y; acc[2]  += xv * w0v.z; acc[3]  += xv * w0v.w;
        acc[4]  += xv * w1v.x; acc[5]  += xv * w1v.y; acc[6]  += xv * w1v.z; acc[7]  += xv * w1v.w;
        acc[8]  += xv * w2v.x; acc[9]  += xv * w2v.y; acc[10] += xv * w2v.z; acc[11] += xv * w2v.w;
        acc[12] += xv * w3v.x; acc[13] += xv * w3v.y; acc[14] += xv * w3v.z; acc[15] += xv * w3v.w;
    }

    if (g < 6) {
        float4* dst = (float4*)&g_T[(size_t)row * 96 + g * 16];
#pragma unroll
        for (int q = 0; q < 4; q++)
            dst[q] = make_float4(acc[q*4], acc[q*4+1], acc[q*4+2], acc[q*4+3]);
    } else {
        int off = (g - 6) * 16;
        float4* dst = (float4*)&g_S[(size_t)row * 96 + off];
#pragma unroll
        for (int q = 0; q < 4; q++)
            dst[q] = make_float4(acc[q*4]   + b0s[off + q*4],
                                 acc[q*4+1] + b0s[off + q*4 + 1],
                                 acc[q*4+2] + b0s[off + q*4 + 2],
                                 acc[q*4+3] + b0s[off + q*4 + 3]);
    }
}

// ---------------------------------------------------------------------------
// Kernel 2: degrees + sagg.  One block per (b,n) row:
//   dis = rsqrt(max(deg,1));  g_sagg[row][ec] = dis[e] * g_T[row][ec]
// ---------------------------------------------------------------------------
__global__ __launch_bounds__(256) void deg_kernel(const float* __restrict__ adj)
{
    int row = blockIdx.x;                    // b*N + n
    const float4* base = (const float4*)(adj + (size_t)row * 3072);
    int t = threadIdx.x;

    float s0 = 0.f, s1 = 0.f, s2 = 0.f;
#pragma unroll 3
    for (int it = 0; it < 3; it++) {
        int q = t + it * 256;                // float4 index, 768 total
        float4 v = base[q];
        int e0 = q % 3;                      // (4q)%3 == q%3
        if (e0 == 0)      { s0 += v.x; s1 += v.y; s2 += v.z; s0 += v.w; }
        else if (e0 == 1) { s1 += v.x; s2 += v.y; s0 += v.z; s1 += v.w; }
        else              { s2 += v.x; s0 += v.y; s1 += v.z; s2 += v.w; }
    }
#pragma unroll
    for (int off = 16; off; off >>= 1) {
        s0 += __shfl_down_sync(0xffffffffu, s0, off);
        s1 += __shfl_down_sync(0xffffffffu, s1, off);
        s2 += __shfl_down_sync(0xffffffffu, s2, off);
    }
    __shared__ float red[8][3];
    __shared__ float dis_s[3];
    int w = t >> 5, lane = t & 31;
    if (lane == 0) { red[w][0] = s0; red[w][1] = s1; red[w][2] = s2; }
    __syncthreads();
    if (t < 3) {
        float tot = 0.f;
#pragma unroll
        for (int i = 0; i < 8; i++) tot += red[i][t];
        float d = rsqrtf(fmaxf(tot, 1.0f));
        dis_s[t] = d;
        g_dis[(size_t)row * 3 + t] = d;
    }
    __syncthreads();
    if (t < 96) g_sagg[(size_t)row * 96 + t] = dis_s[t >> 5] * g_T[(size_t)row * 96 + t];
}

// ---------------------------------------------------------------------------
// Kernel 3: aggregation GEMM, register-only (no smem), k-split warps.
//   out[b,n,c] = mask * ( sum_e dis[n,e] * sum_{k'} adj[n][k'] * sagg[k'][c]
//                         + sum_e S[n][e*32+c] ),  k' = m*3+e, K=3072
// Block = 256 thr (8 warps), 32 n rows; warp w owns rows 4w..4w+3.
// Lane = (ng = lane>>3, cg = lane&7): thread computes c = 4cg..4cg+3 over the
// k'-partition {g*48 + ng*12 + j, j<12}; e = j%3 is compile-time.  A loads are
// uniform-per-octet LDG.128 (<=2 lines/instr); B loads span one 128B line.
// Per-e f32x2 accumulators, shfl-reduced over ng at the end.
// ---------------------------------------------------------------------------
__global__ __launch_bounds__(256, 2) void agg_kernel(
    const float* __restrict__ adj,
    const int* __restrict__ mask,
    float* __restrict__ out)
{
    int t = threadIdx.x, w = t >> 5, lane = t & 31;
    int ng = lane >> 3, cg = lane & 7;
    int b = blockIdx.y;
    int nbase = blockIdx.x * 32 + w * 4;

    const float* adjb = adj + ((size_t)b * Nn + nbase) * 3072;   // + r*3072 + k'
    const float* sb   = g_sagg + (size_t)b * Nn * 96 + cg * 4;   // + k'*32

    unsigned long long acc[4][2][3];
#pragma unroll
    for (int r = 0; r < 4; r++)
#pragma unroll
        for (int cp = 0; cp < 2; cp++)
#pragma unroll
            for (int e = 0; e < 3; e++) acc[r][cp][e] = 0ull;

    for (int g = 0; g < 64; g++) {                    // 48 k' per group
        const float* ap = adjb + g * 48 + ng * 12;    // this thread's 12 k'
        const float* bp = sb + (size_t)(g * 48 + ng * 12) * 32;
#pragma unroll
        for (int q = 0; q < 3; q++) {                 // 4 k' per sub-quad
            float4 A0 = *(const float4*)(ap            + q * 4);
            float4 A1 = *(const float4*)(ap + 1 * 3072 + q * 4);
            float4 A2 = *(const float4*)(ap + 2 * 3072 + q * 4);
            float4 A3 = *(const float4*)(ap + 3 * 3072 + q * 4);
#pragma unroll
            for (int j4 = 0; j4 < 4; j4++) {
                const int e = (q * 4 + j4) % 3;       // compile-time
                ulonglong2 bv = *(const ulonglong2*)(bp + (size_t)(q * 4 + j4) * 32);
                unsigned long long a2;
                float a;
                a = GETC(A0, j4); DUP2(a2, a);
                FFMA2(acc[0][0][e], a2, bv.x); FFMA2(acc[0][1][e], a2, bv.y);
                a = GETC(A1, j4); DUP2(a2, a);
                FFMA2(acc[1][0][e], a2, bv.x); FFMA2(acc[1][1][e], a2, bv.y);
                a = GETC(A2, j4); DUP2(a2, a);
                FFMA2(acc[2][0][e], a2, bv.x); FFMA2(acc[2][1][e], a2, bv.y);
                a = GETC(A3, j4); DUP2(a2, a);
                FFMA2(acc[3][0][e], a2, bv.x); FFMA2(acc[3][1][e], a2, bv.y);
            }
        }
    }

    // unpack + reduce the 4 ng-partials (lanes xor 8, xor 16)
    float accf[4][4][3];
#pragma unroll
    for (int r = 0; r < 4; r++)
#pragma unroll
        for (int cp = 0; cp < 2; cp++)
#pragma unroll
            for (int e = 0; e < 3; e++) {
                float lo, hi;
                UNPACK2(lo, hi, acc[r][cp][e]);
                lo += __shfl_xor_sync(0xffffffffu, lo, 8);
                hi += __shfl_xor_sync(0xffffffffu, hi, 8);
                lo += __shfl_xor_sync(0xffffffffu, lo, 16);
                hi += __shfl_xor_sync(0xffffffffu, hi, 16);
                accf[r][cp * 2][e]     = lo;
                accf[r][cp * 2 + 1][e] = hi;
            }

    if (ng == 0) {
#pragma unroll
        for (int r = 0; r < 4; r++) {
            size_t rown = (size_t)b * Nn + nbase + r;
            float d0 = g_dis[rown * 3 + 0];
            float d1 = g_dis[rown * 3 + 1];
            float d2 = g_dis[rown * 3 + 2];
            const float* Sp = g_S + rown * 96 + cg * 4;
            float4 S0 = *(const float4*)(Sp);
            float4 S1 = *(const float4*)(Sp + 32);
            float4 S2 = *(const float4*)(Sp + 64);
            int mk = mask[rown];
            float4 o;
            o.x = d0*accf[r][0][0] + d1*accf[r][0][1] + d2*accf[r][0][2] + S0.x + S1.x + S2.x;
            o.y = d0*accf[r][1][0] + d1*accf[r][1][1] + d2*accf[r][1][2] + S0.y + S1.y + S2.y;
            o.z = d0*accf[r][2][0] + d1*accf[r][2][1] + d2*accf[r][2][2] + S0.z + S1.z + S2.z;
            o.w = d0*accf[r][3][0] + d1*accf[r][3][1] + d2*accf[r][3][2] + S0.w + S1.w + S2.w;
            if (mk == 0) { o.x = 0.f; o.y = 0.f; o.z = 0.f; o.w = 0.f; }
            *(float4*)(out + rown * 32 + cg * 4) = o;
        }
    }
}

// ---------------------------------------------------------------------------
extern "C" void kernel_launch(void* const* d_in, const int* in_sizes, int n_in,
                              void* d_out, int out_size)
{
    const float* x    = (const float*)d_in[0];   // [16,1024,32]
    const float* adj  = (const float*)d_in[1];   // [16,1024,1024,3]
    const int*   mask = (const int*)d_in[2];     // [16,1024] bool -> int32
    const float* W    = (const float*)d_in[3];   // [32,96]
    const float* W0   = (const float*)d_in[4];   // [32,96]
    const float* b0   = (const float*)d_in[5];   // [96]
    float*       out  = (float*)d_out;           // [16,1024,32]

    (void)in_sizes; (void)n_in; (void)out_size;

    prep_kernel<<<512, 384>>>(x, W, W0, b0);
    deg_kernel<<<Bn * Nn, 256>>>(adj);
    agg_kernel<<<dim3(Nn / 32, Bn), 256>>>(adj, mask, out);
}

// round 8
// speedup vs baseline: 1.3702x; 1.3702x over previous
#include <cuda_runtime.h>
#include <cstdint>

#define Bn  16
#define Nn  1024

// Scratch (device globals; no allocation allowed)
__device__ __align__(16) float g_S[Bn * Nn * 96];     // x @ W0 + b0      [row][ec]
__device__ __align__(16) float g_sagg[Bn * Nn * 96];  // dis[m,e]*(x@W)   [row][ec]
__device__ __align__(16) float g_dis[Bn * Nn * 3];    // deg^-1/2         [row][e]

__device__ __forceinline__ uint32_t sptr(const void* p) {
    return (uint32_t)__cvta_generic_to_shared(p);
}
#define FFMA2(d, a, b) \
    asm volatile("fma.rn.f32x2 %0, %1, %2, %0;" : "+l"(d) : "l"(a), "l"(b))
#define DUP2(d, a) \
    asm volatile("mov.b64 %0, {%1,%1};" : "=l"(d) : "f"(a))
#define UNPACK2(lo, hi, v) \
    asm volatile("mov.b64 {%0,%1}, %2;" : "=f"(lo), "=f"(hi) : "l"(v))
#define CPASYNC16(dst, src) \
    asm volatile("cp.async.cg.shared.global [%0], [%1], 16;" :: "r"(dst), "l"(src))
#define GETC(v, j) ((j) == 0 ? (v).x : (j) == 1 ? (v).y : (j) == 2 ? (v).z : (v).w)

// ---------------------------------------------------------------------------
// Kernel 1 (fused): degrees + per-row linears.
// One block per (b,n) row:
//   deg[e] = sum_m adj[row][m][e];  dis = rsqrt(max(deg,1))  -> g_dis
//   g_sagg[row][ec] = dis[e] * (x[row] @ W)[ec]
//   g_S   [row][ec] = (x[row] @ W0)[ec] + b0[ec]
// The 0.2-GFLOP linear work rides in the epilogue of the DRAM-bound adj scan
// (W/W0 stay L1-resident across the many blocks per SM).
// ---------------------------------------------------------------------------
__global__ __launch_bounds__(256) void deg_kernel(
    const float* __restrict__ adj,
    const float* __restrict__ x,
    const float* __restrict__ W,
    const float* __restrict__ W0,
    const float* __restrict__ b0)
{
    int row = blockIdx.x;                    // b*N + n
    const float4* base = (const float4*)(adj + (size_t)row * 3072);
    int t = threadIdx.x;

    __shared__ float xsh[32];
    if (t < 32) xsh[t] = x[(size_t)row * 32 + t];

    float s0 = 0.f, s1 = 0.f, s2 = 0.f;
#pragma unroll 3
    for (int it = 0; it < 3; it++) {
        int q = t + it * 256;                // float4 index, 768 total
        float4 v = base[q];
        int e0 = q % 3;                      // (4q)%3 == q%3
        if (e0 == 0)      { s0 += v.x; s1 += v.y; s2 += v.z; s0 += v.w; }
        else if (e0 == 1) { s1 += v.x; s2 += v.y; s0 += v.z; s1 += v.w; }
        else              { s2 += v.x; s0 += v.y; s1 += v.z; s2 += v.w; }
    }
#pragma unroll
    for (int off = 16; off; off >>= 1) {
        s0 += __shfl_down_sync(0xffffffffu, s0, off);
        s1 += __shfl_down_sync(0xffffffffu, s1, off);
        s2 += __shfl_down_sync(0xffffffffu, s2, off);
    }
    __shared__ float red[8][3];
    __shared__ float dis_s[3];
    int w = t >> 5, lane = t & 31;
    if (lane == 0) { red[w][0] = s0; red[w][1] = s1; red[w][2] = s2; }
    __syncthreads();
    if (t < 3) {
        float tot = 0.f;
#pragma unroll
        for (int i = 0; i < 8; i++) tot += red[i][t];
        float d = rsqrtf(fmaxf(tot, 1.0f));
        dis_s[t] = d;
        g_dis[(size_t)row * 3 + t] = d;
    }
    __syncthreads();

    // fused linear epilogue: 192 threads, 32 FMA each
    if (t < 192) {
        int ec = t % 96;
        const float* Wp = ((t < 96) ? W : W0) + ec;
        float a = 0.f;
#pragma unroll
        for (int k = 0; k < 32; k++) a += xsh[k] * __ldg(Wp + k * 96);
        if (t < 96) g_sagg[(size_t)row * 96 + ec] = dis_s[ec >> 5] * a;
        else        g_S[(size_t)row * 96 + ec]    = a + __ldg(b0 + ec);
    }
}

// ---------------------------------------------------------------------------
// Kernel 2: fused aggregation GEMM.
//   out[b,n,c] = mask * ( sum_e dis[n,e] * sum_m adj[b,n,m,e]*sagg[b,m,ec]
//                         + sum_e S[b,n,e*32+c] )
// Block = 256 thr (8 warps), n-tile 64; warp w owns rows 8w..8w+7.
// Lane = (rp = lane>>3, cq = lane&7): lane computes rows {2rp, 2rp+1} for
// channels c = 4cq..4cq+3.  m streamed in chunks of 32:
//   - sagg chunk (one contiguous 12 KB span of g_sagg) double-buffered via
//     cp.async; consumed as LDS.128 c-quads broadcast over rp (1 wavefront);
//     the two f32x2 c-pairs come straight out of a ulonglong2 load.
//   - adj goes global->registers (LDG.128 per row-quad; never touches smem),
//     scalar dup'd with one mov.b64 per FFMA2 pair (alu pipe).
// Per-e f32x2 accumulators; no cross-lane reduction needed.
// ---------------------------------------------------------------------------
__global__ __launch_bounds__(256, 2) void agg_kernel(
    const float* __restrict__ adj,
    const int* __restrict__ mask,
    float* __restrict__ out)
{
    __shared__ __align__(16) float sg[2][32 * 96];   // 2 x 12 KB

    int t = threadIdx.x, w = t >> 5, lane = t & 31;
    int rp = lane >> 3, cq = lane & 7;
    int b = blockIdx.y, n0 = blockIdx.x * 64;

    int rowA = n0 + w * 8 + 2 * rp;                   // lane's even row
    const float* adjA = adj + ((size_t)b * Nn + rowA) * 3072;
    const float* adjB = adjA + 3072;                  // odd row
    const float* sgg  = g_sagg + ((size_t)b * Nn) * 96;

    uint32_t sg_base = sptr(&sg[0][0]);

    // cp.async fill: 3 x 16B per thread per chunk (12 KB total)
    auto cp_sagg = [&](int s, int m0) {
        const float* src = sgg + (size_t)m0 * 96;     // contiguous 3072 floats
        uint32_t dst = sg_base + (uint32_t)s * 12288u;
#pragma unroll
        for (int it = 0; it < 3; it++) {
            int q = t + it * 256;
            CPASYNC16(dst + (uint32_t)q * 16u, src + q * 4);
        }
        asm volatile("cp.async.commit_group;" ::: "memory");
    };

    unsigned long long acc2[2][2][3];                 // [rsel][cpair][e]
#pragma unroll
    for (int r = 0; r < 2; r++)
#pragma unroll
        for (int p = 0; p < 2; p++)
#pragma unroll
            for (int e = 0; e < 3; e++) acc2[r][p][e] = 0ull;

    cp_sagg(0, 0);

    for (int k = 0; k < 32; k++) {
        int cb = k & 1;
        if (k < 31) cp_sagg(cb ^ 1, (k + 1) * 32);
        asm volatile("cp.async.wait_group %0;" :: "n"(1) : "memory");
        if (k == 31) asm volatile("cp.async.wait_group 0;" ::: "memory");
        __syncthreads();                              // chunk k visible to all

        int m0 = k * 32;

#pragma unroll
        for (int qq = 0; qq < 8; qq++) {              // 4-m quads
            // adj: 12 k' per row, straight to registers
            float4 A0[3], A1[3];
            int koff = (m0 + 4 * qq) * 3;
#pragma unroll
            for (int s = 0; s < 3; s++) {
                A0[s] = *(const float4*)(adjA + koff + s * 4);
                A1[s] = *(const float4*)(adjB + koff + s * 4);
            }
#pragma unroll
            for (int ml = 0; ml < 4; ml++) {          // m within quad
                ulonglong2 sv[3];
#pragma unroll
                for (int e = 0; e < 3; e++)
                    sv[e] = *(const ulonglong2*)&sg[cb][(4 * qq + ml) * 96 + e * 32 + cq * 4];
#pragma unroll
                for (int e = 0; e < 3; e++) {
                    const int kl = ml * 3 + e;        // k' local in quad, e = kl%3
                    const int s = kl >> 2, cmp = kl & 3;
                    unsigned long long a2;
                    float a;
                    a = GETC(A0[s], cmp); DUP2(a2, a);
                    FFMA2(acc2[0][0][e], a2, sv[e].x);
                    FFMA2(acc2[0][1][e], a2, sv[e].y);
                    a = GETC(A1[s], cmp); DUP2(a2, a);
                    FFMA2(acc2[1][0][e], a2, sv[e].x);
                    FFMA2(acc2[1][1][e], a2, sv[e].y);
                }
            }
        }
        __syncthreads();                              // all reads of buf done
    }

    // epilogue
#pragma unroll
    for (int r = 0; r < 2; r++) {
        int n = rowA + r;
        size_t rown = (size_t)b * Nn + n;
        float d0 = g_dis[rown * 3 + 0];
        float d1 = g_dis[rown * 3 + 1];
        float d2 = g_dis[rown * 3 + 2];
        const float* Sp = g_S + rown * 96 + cq * 4;
        float4 S0 = *(const float4*)(Sp);
        float4 S1 = *(const float4*)(Sp + 32);
        float4 S2 = *(const float4*)(Sp + 64);
        float lo, hi;
        float4 o;
        UNPACK2(lo, hi, acc2[r][0][0]);
        o.x = d0 * lo; o.y = d0 * hi;
        UNPACK2(lo, hi, acc2[r][0][1]);
        o.x += d1 * lo; o.y += d1 * hi;
        UNPACK2(lo, hi, acc2[r][0][2]);
        o.x += d2 * lo; o.y += d2 * hi;
        UNPACK2(lo, hi, acc2[r][1][0]);
        o.z = d0 * lo; o.w = d0 * hi;
        UNPACK2(lo, hi, acc2[r][1][1]);
        o.z += d1 * lo; o.w += d1 * hi;
        UNPACK2(lo, hi, acc2[r][1][2]);
        o.z += d2 * lo; o.w += d2 * hi;
        o.x += S0.x + S1.x + S2.x;
        o.y += S0.y + S1.y + S2.y;
        o.z += S0.z + S1.z + S2.z;
        o.w += S0.w + S1.w + S2.w;
        if (mask[rown] == 0) { o.x = 0.f; o.y = 0.f; o.z = 0.f; o.w = 0.f; }
        *(float4*)(out + rown * 32 + cq * 4) = o;
    }
}

// ---------------------------------------------------------------------------
extern "C" void kernel_launch(void* const* d_in, const int* in_sizes, int n_in,
                              void* d_out, int out_size)
{
    const float* x    = (const float*)d_in[0];   // [16,1024,32]
    const float* adj  = (const float*)d_in[1];   // [16,1024,1024,3]
    const int*   mask = (const int*)d_in[2];     // [16,1024] bool -> int32
    const float* W    = (const float*)d_in[3];   // [32,96]
    const float* W0   = (const float*)d_in[4];   // [32,96]
    const float* b0   = (const float*)d_in[5];   // [96]
    float*       out  = (float*)d_out;           // [16,1024,32]

    (void)in_sizes; (void)n_in; (void)out_size;

    deg_kernel<<<Bn * Nn, 256>>>(adj, x, W, W0, b0);
    agg_kernel<<<dim3(Nn / 64, Bn), 256>>>(adj, mask, out);
}